// round 6
// baseline (speedup 1.0000x reference)
#include <cuda_runtime.h>
#include <cstdint>

// ---------------------------------------------------------------------------
// Problem constants
// ---------------------------------------------------------------------------
#define NWIN   65536
#define DIM    128
#define KCB    2048
#define MT     128              // windows per CTA
#define NSTG   64               // pipeline stages: (tile, k32) pairs
#define STG_FLOATS 4096         // one stage = 16 KB: k32 x ch frag image

// main-kernel smem layout (float offsets)
#define ZH_OFF   0              // zh frag image: 16 sg x 8 mf x 32 lane x 4
#define BB_OFF   16384          // B double buffer: 2 x 4096
#define CN_OFF   24576          // 2048 codebook norms
#define SMEM_FLOATS 26624
#define SMEM_BYTES  (SMEM_FLOATS * 4)

#define TAU 0.25f               // rescue threshold on approx min2-min1 gap

__device__ float g_cnorm[KCB];
__device__ float g_Bimg[NSTG * STG_FLOATS];   // 1 MB fragment-major tf32 image
__device__ int   g_rcnt;
__device__ int   g_rlist[NWIN];

// ---------------------------------------------------------------------------
// Helpers
// ---------------------------------------------------------------------------
__device__ __forceinline__ uint32_t to_tf32(float x) {
    uint32_t r;
    asm("cvt.rna.tf32.f32 %0, %1;" : "=r"(r) : "f"(x));
    return r;
}
__device__ __forceinline__ uint32_t smem_u32(const void* p) {
    uint32_t a;
    asm("{ .reg .u64 t; cvta.to.shared.u64 t, %1; cvt.u32.u64 %0, t; }"
        : "=r"(a) : "l"(p));
    return a;
}
__device__ __forceinline__ void fma_f32x2(unsigned long long& acc,
                                          unsigned long long a,
                                          unsigned long long b) {
    asm("fma.rn.f32x2 %0, %1, %2, %0;" : "+l"(acc) : "l"(a), "l"(b));
}
__device__ __forceinline__ float pair_sum(unsigned long long p) {
    return __uint_as_float((unsigned)(p & 0xFFFFFFFFull))
         + __uint_as_float((unsigned)(p >> 32));
}

// m16n8k8 tf32 MMA, D += A*B (fp32 accum)
#define MMA(d, a, b) \
    asm volatile("mma.sync.aligned.m16n8k8.row.col.f32.tf32.tf32.f32 " \
        "{%0,%1,%2,%3},{%4,%5,%6,%7},{%8,%9},{%0,%1,%2,%3};" \
        : "+f"((d)[0]), "+f"((d)[1]), "+f"((d)[2]), "+f"((d)[3]) \
        : "r"((a)[0]), "r"((a)[1]), "r"((a)[2]), "r"((a)[3]), \
          "r"((b)[0]), "r"((b)[1]))

#define CP16(dst, src) \
    asm volatile("cp.async.cg.shared.global [%0], [%1], 16;" \
                 :: "r"(dst), "l"(src) : "memory")
#define CP_COMMIT() asm volatile("cp.async.commit_group;" ::: "memory")

// ---------------------------------------------------------------------------
// Prep 1: codebook squared norms (exact fp32); also zero the rescue counter.
// ---------------------------------------------------------------------------
__global__ void cnorm_kernel(const float* __restrict__ cb) {
    if (blockIdx.x == 0 && threadIdx.x == 0) g_rcnt = 0;
    int warp = (blockIdx.x * blockDim.x + threadIdx.x) >> 5;
    int lane = threadIdx.x & 31;
    if (warp >= KCB) return;
    const float4* row = (const float4*)(cb + (size_t)warp * DIM);
    float4 v = row[lane];
    float s = v.x * v.x + v.y * v.y + v.z * v.z + v.w * v.w;
    #pragma unroll
    for (int o = 16; o; o >>= 1) s += __shfl_xor_sync(0xFFFFFFFFu, s, o);
    if (lane == 0) g_cnorm[warp] = s;
}

// ---------------------------------------------------------------------------
// Prep 2: fragment-major tf32 B image (ch only).
// Stage stg = (tile t, k32-stage st). Element:
//   i = (s*16 + f)*64 + lane*2 + reg
//   code n = t*128 + f*8 + (lane>>2),  k = st*32 + s*8 + (lane&3) + 4*reg
// Matches the mma.sync B-fragment so main-kernel B loads are single LDS.64s.
// ---------------------------------------------------------------------------
__global__ __launch_bounds__(256) void bprep_kernel(const float* __restrict__ cb) {
    int stg = blockIdx.x;
    int t = stg >> 2, st = stg & 3;
    for (int i = threadIdx.x; i < STG_FLOATS; i += 256) {
        int reg  = i & 1;
        int lane = (i >> 1) & 31;
        int f    = (i >> 6) & 15;
        int s    = (i >> 10) & 3;
        int n = t * 128 + f * 8 + (lane >> 2);
        int k = st * 32 + s * 8 + (lane & 3) + 4 * reg;
        g_Bimg[(size_t)stg * STG_FLOATS + i] =
            __uint_as_float(to_tf32(cb[(size_t)n * DIM + k]));
    }
}

// ---------------------------------------------------------------------------
// Main kernel: 1-term tf32 approx GEMM + top-2 argmin + flagging.
//   8 warps = 2(m) x 4(n); warp tile 64 rows x 32 codes.
// ---------------------------------------------------------------------------
__global__ __launch_bounds__(256, 1)
void vq_main(const float* __restrict__ ze,
             const float* __restrict__ cb,
             float* __restrict__ out) {
    extern __shared__ float sm[];
    const uint32_t sb = smem_u32(sm);
    const int tid  = threadIdx.x;
    const int wid  = tid >> 5;
    const int lane = tid & 31;
    const int wm   = wid & 1;
    const int wn   = wid >> 1;
    const int m0   = blockIdx.x * MT;

    // prime B pipeline: stage 0 -> buffer 0 (4 x 16B per thread)
    {
        const float* src = g_Bimg + tid * 4;
        uint32_t dst = sb + (BB_OFF + tid * 4) * 4;
        #pragma unroll
        for (int j = 0; j < 4; j++) CP16(dst + j * 4096, src + j * 1024);
        CP_COMMIT();
    }

    for (int i = tid; i < KCB; i += 256) sm[CN_OFF + i] = g_cnorm[i];

    // zh fragment image: idx ((sg*8+mf)*32+l)*4+reg
    //   m = mf*16 + (l>>2) + 8*(reg&1), k = sg*8 + (l&3) + 4*(reg>>1)
    for (int i = tid; i < MT * DIM; i += 256) {
        int m = i >> 7, k = i & 127;
        float v = ze[(size_t)(m0 + m) * DIM + k];
        int sg = k >> 3, mf = m >> 4, r = m & 15;
        int l   = ((r & 7) << 2) | (k & 3);
        int reg = (((k >> 2) & 1) << 1) | (r >> 3);
        sm[ZH_OFF + ((sg * 8 + mf) * 32 + l) * 4 + reg] =
            __uint_as_float(to_tf32(v));
    }

    float acc[4][4][4];
    #pragma unroll
    for (int a = 0; a < 4; a++)
        #pragma unroll
        for (int b = 0; b < 4; b++)
            #pragma unroll
            for (int c = 0; c < 4; c++) acc[a][b][c] = 0.0f;

    float minv[8], minv2[8];
    int   mini[8];
    #pragma unroll
    for (int i = 0; i < 8; i++) { minv[i] = 3.4e38f; minv2[i] = 3.4e38f; mini[i] = 0; }

    const uint4* ZH = (const uint4*)(sm + ZH_OFF);

    for (int st = 0; st < NSTG; st++) {
        if (st < NSTG - 1) {
            const float* src = g_Bimg + (size_t)(st + 1) * STG_FLOATS + tid * 4;
            uint32_t dst = sb + (BB_OFF + ((st + 1) & 1) * STG_FLOATS + tid * 4) * 4;
            #pragma unroll
            for (int j = 0; j < 4; j++) CP16(dst + j * 4096, src + j * 1024);
            CP_COMMIT();
            asm volatile("cp.async.wait_group 1;" ::: "memory");
        } else {
            asm volatile("cp.async.wait_group 0;" ::: "memory");
        }
        __syncthreads();

        const uint2* Bp = (const uint2*)(sm + BB_OFF + (st & 1) * STG_FLOATS);
        const int sti = st & 3;

        #pragma unroll
        for (int s = 0; s < 4; s++) {
            const int sg = sti * 4 + s;
            uint32_t ah[4][4], bh[4][2];
            #pragma unroll
            for (int mf = 0; mf < 4; mf++) {
                uint4 h = ZH[(sg * 8 + wm * 4 + mf) * 32 + lane];
                ah[mf][0] = h.x; ah[mf][1] = h.y; ah[mf][2] = h.z; ah[mf][3] = h.w;
            }
            #pragma unroll
            for (int f = 0; f < 4; f++) {
                uint2 h = Bp[((s * 16) + wn * 4 + f) * 32 + lane];
                bh[f][0] = h.x; bh[f][1] = h.y;
            }
            #pragma unroll
            for (int mf = 0; mf < 4; mf++)
                #pragma unroll
                for (int f = 0; f < 4; f++)
                    MMA(acc[mf][f], ah[mf], bh[f]);
        }

        if (sti == 3) {
            const int t  = st >> 2;
            const int kb = t * 128 + wn * 32 + 2 * (lane & 3);
            #pragma unroll
            for (int mf = 0; mf < 4; mf++)
                #pragma unroll
                for (int f = 0; f < 4; f++)
                    #pragma unroll
                    for (int c = 0; c < 4; c++) {
                        int kn = kb + f * 8 + (c & 1);
                        float sc = fmaf(-2.0f, acc[mf][f][c], sm[CN_OFF + kn]);
                        int i = mf * 2 + (c >> 1);
                        if (sc < minv[i]) {
                            minv2[i] = minv[i]; minv[i] = sc; mini[i] = kn;
                        } else if (sc < minv2[i]) {
                            minv2[i] = sc;
                        }
                        acc[mf][f][c] = 0.0f;
                    }
        }
        __syncthreads();
    }

    // cross-thread top-2 combine (16 partials per row)
    float* rv1  = sm + BB_OFF;                   // [128][16]
    int*   ri1  = (int*)(sm + BB_OFF + 2048);
    float* rv2  = sm + BB_OFF + 4096;
    int*   fidx = (int*)(sm + BB_OFF + 6144);
    #pragma unroll
    for (int i = 0; i < 8; i++) {
        int mfl = i >> 1, rh = i & 1;
        int m = wm * 64 + mfl * 16 + rh * 8 + (lane >> 2);
        int slot = wn * 4 + (lane & 3);
        rv1[m * 16 + slot] = minv[i];
        ri1[m * 16 + slot] = mini[i];
        rv2[m * 16 + slot] = minv2[i];
    }
    __syncthreads();
    if (tid < MT) {
        float m1 = rv1[tid * 16], m2 = rv2[tid * 16];
        int   i1 = ri1[tid * 16];
        #pragma unroll
        for (int t = 1; t < 16; t++) {
            float v1 = rv1[tid * 16 + t], v2 = rv2[tid * 16 + t];
            int  id = ri1[tid * 16 + t];
            if (v1 < m1 || (v1 == m1 && id < i1)) {
                m2 = fminf(m1, v2); m1 = v1; i1 = id;
            } else {
                m2 = fminf(m2, v1);
            }
        }
        fidx[tid] = i1;
        if (m2 - m1 < TAU) {
            int p = atomicAdd(&g_rcnt, 1);
            g_rlist[p] = m0 + tid;
        }
    }
    __syncthreads();

    // gather + write output (rescue overwrites flagged rows later)
    const float4* cb4 = (const float4*)cb;
    float4* out4 = (float4*)out;
    for (int i = tid; i < MT * (DIM / 4); i += 256) {
        int m = i >> 5, c = i & 31;
        out4[(size_t)(m0 + m) * 32 + c] = cb4[(size_t)fidx[m] * 32 + c];
    }
}

// ---------------------------------------------------------------------------
// Rescue: exact fp32 full 2048-scan for flagged rows. 16 rows/block.
//   smem codebook tile [128][130] (pad 130 + k=g+16j interleave: conflict-free)
// ---------------------------------------------------------------------------
#define RPB 16
#define ZPAD 130
// dynamic smem floats: zt 16*130 + ct 128*130 + red 2*16*17 + list 16
#define RS_ZT   0
#define RS_CT   (RPB * ZPAD)                    // 2080
#define RS_RBV  (RS_CT + 128 * ZPAD)            // 18720
#define RS_RBK  (RS_RBV + RPB * 17)             // 18992
#define RS_LIST (RS_RBK + RPB * 17)             // 19264
#define RS_FLOATS 19280
#define RS_BYTES  (RS_FLOATS * 4)

__global__ __launch_bounds__(256, 1)
void rescue_kernel(const float* __restrict__ ze,
                   const float* __restrict__ cb,
                   float* __restrict__ out) {
    const int base = blockIdx.x * RPB;
    const int cnt = g_rcnt;
    if (base >= cnt) return;
    const int nrows = min(RPB, cnt - base);

    extern __shared__ float rs[];
    float* zt  = rs + RS_ZT;
    float* ct  = rs + RS_CT;
    float* rbv = rs + RS_RBV;
    int*   rbk = (int*)(rs + RS_RBK);
    int*   lst = (int*)(rs + RS_LIST);

    const int tid = threadIdx.x;
    const int r = tid >> 4;          // row slot 0..15
    const int g = tid & 15;          // code group 0..15

    if (tid < RPB) lst[tid] = (tid < nrows) ? g_rlist[base + tid] : 0;
    __syncthreads();

    // load z rows
    for (int i = tid; i < nrows * DIM; i += 256) {
        int rr = i >> 7, d = i & 127;
        zt[rr * ZPAD + d] = ze[(size_t)lst[rr] * DIM + d];
    }

    float bv = 3.4e38f;
    int   bk = 0;

    for (int t = 0; t < KCB / 128; t++) {
        __syncthreads();
        for (int i = tid; i < 128 * DIM; i += 256) {
            int kk = i >> 7, d = i & 127;
            ct[kk * ZPAD + d] = cb[(size_t)(t * 128 + kk) * DIM + d];
        }
        __syncthreads();
        if (r < nrows) {
            const unsigned long long* z2 =
                (const unsigned long long*)(zt + r * ZPAD);
            #pragma unroll
            for (int j = 0; j < 8; j++) {
                int k = g + 16 * j;
                const unsigned long long* c2 =
                    (const unsigned long long*)(ct + k * ZPAD);
                unsigned long long a0 = 0, a1 = 0;
                #pragma unroll 8
                for (int d2 = 0; d2 < 64; d2 += 2) {
                    fma_f32x2(a0, z2[d2],     c2[d2]);
                    fma_f32x2(a1, z2[d2 + 1], c2[d2 + 1]);
                }
                int kg = t * 128 + k;
                float s = fmaf(-2.0f, pair_sum(a0) + pair_sum(a1), g_cnorm[kg]);
                if (s < bv || (s == bv && kg < bk)) { bv = s; bk = kg; }
            }
        }
    }
    __syncthreads();
    rbv[r * 17 + g] = bv;
    rbk[r * 17 + g] = bk;
    __syncthreads();

    if (tid < nrows) {
        float m1 = rbv[tid * 17];
        int   i1 = rbk[tid * 17];
        #pragma unroll
        for (int t = 1; t < 16; t++) {
            float v = rbv[tid * 17 + t];
            int  id = rbk[tid * 17 + t];
            if (v < m1 || (v == m1 && id < i1)) { m1 = v; i1 = id; }
        }
        rbk[tid * 17] = i1;
    }
    __syncthreads();

    for (int i = tid; i < nrows * DIM; i += 256) {
        int rr = i >> 7, d = i & 127;
        out[(size_t)lst[rr] * DIM + d] = cb[(size_t)rbk[rr * 17] * DIM + d];
    }
}

// ---------------------------------------------------------------------------
extern "C" void kernel_launch(void* const* d_in, const int* in_sizes, int n_in,
                              void* d_out, int out_size) {
    const float* ze = (const float*)d_in[0];   // [65536, 128]
    const float* cb = (const float*)d_in[1];   // [2048, 128]
    float* out = (float*)d_out;
    (void)in_sizes; (void)n_in; (void)out_size;

    cudaFuncSetAttribute(vq_main,
                         cudaFuncAttributeMaxDynamicSharedMemorySize, SMEM_BYTES);
    cudaFuncSetAttribute(rescue_kernel,
                         cudaFuncAttributeMaxDynamicSharedMemorySize, RS_BYTES);

    cnorm_kernel<<<KCB / 8, 256>>>(cb);
    bprep_kernel<<<NSTG, 256>>>(cb);
    vq_main<<<NWIN / MT, 256, SMEM_BYTES>>>(ze, cb, out);
    rescue_kernel<<<NWIN / RPB, 256, RS_BYTES>>>(ze, cb, out);
}

// round 7
// speedup vs baseline: 2.1869x; 2.1869x over previous
#include <cuda_runtime.h>
#include <cuda_fp16.h>
#include <cstdint>

// ---------------------------------------------------------------------------
// Problem constants
// ---------------------------------------------------------------------------
#define NWIN   65536
#define DIM    128
#define KCB    2048
#define MT     128              // windows per CTA
#define NSTG   32               // stages: (tile, k64-chunk)
#define STG_UINTS 4096          // one stage = 16 KB fp16 frag image

// main-kernel smem layout (float offsets)
#define ZH_OFF   0              // zh fp16 frag image: 8 ks x 8 mf x 32 lane x uint4
#define BB_OFF   8192           // B double buffer: 2 x 4096 uints
#define CN_OFF   16384          // 2048 codebook norms
#define SMEM_FLOATS 18432
#define SMEM_BYTES  (SMEM_FLOATS * 4)

#define TAU 0.18f               // rescue threshold on approx min2-min1 gap

__device__ float    g_cnorm[KCB];
__device__ uint32_t g_Bimg[NSTG * STG_UINTS];   // 512 KB fp16 fragment image
__device__ int      g_rcnt;
__device__ int      g_rlist[NWIN];

// ---------------------------------------------------------------------------
// Helpers
// ---------------------------------------------------------------------------
__device__ __forceinline__ uint32_t smem_u32(const void* p) {
    uint32_t a;
    asm("{ .reg .u64 t; cvta.to.shared.u64 t, %1; cvt.u32.u64 %0, t; }"
        : "=r"(a) : "l"(p));
    return a;
}
__device__ __forceinline__ void fma_f32x2(unsigned long long& acc,
                                          unsigned long long a,
                                          unsigned long long b) {
    asm("fma.rn.f32x2 %0, %1, %2, %0;" : "+l"(acc) : "l"(a), "l"(b));
}
__device__ __forceinline__ float pair_sum(unsigned long long p) {
    return __uint_as_float((unsigned)(p & 0xFFFFFFFFull))
         + __uint_as_float((unsigned)(p >> 32));
}

// m16n8k16 fp16 MMA, fp32 accum: D += A*B
#define MMA16(d, a, b) \
    asm volatile("mma.sync.aligned.m16n8k16.row.col.f32.f16.f16.f32 " \
        "{%0,%1,%2,%3},{%4,%5,%6,%7},{%8,%9},{%0,%1,%2,%3};" \
        : "+f"((d)[0]), "+f"((d)[1]), "+f"((d)[2]), "+f"((d)[3]) \
        : "r"((a)[0]), "r"((a)[1]), "r"((a)[2]), "r"((a)[3]), \
          "r"((b)[0]), "r"((b)[1]))

#define CP16(dst, src) \
    asm volatile("cp.async.cg.shared.global [%0], [%1], 16;" \
                 :: "r"(dst), "l"(src) : "memory")
#define CP_COMMIT() asm volatile("cp.async.commit_group;" ::: "memory")

// ---------------------------------------------------------------------------
// Prep 1: codebook squared norms (exact fp32); zero rescue counter.
// ---------------------------------------------------------------------------
__global__ void cnorm_kernel(const float* __restrict__ cb) {
    if (blockIdx.x == 0 && threadIdx.x == 0) g_rcnt = 0;
    int warp = (blockIdx.x * blockDim.x + threadIdx.x) >> 5;
    int lane = threadIdx.x & 31;
    if (warp >= KCB) return;
    const float4* row = (const float4*)(cb + (size_t)warp * DIM);
    float4 v = row[lane];
    float s = v.x * v.x + v.y * v.y + v.z * v.z + v.w * v.w;
    #pragma unroll
    for (int o = 16; o; o >>= 1) s += __shfl_xor_sync(0xFFFFFFFFu, s, o);
    if (lane == 0) g_cnorm[warp] = s;
}

// ---------------------------------------------------------------------------
// Prep 2: fragment-major fp16 B image.
// Stage stg = (tile t = stg>>1, k64-chunk kc = stg&1). Element:
//   i = ((ks*16 + f)*32 + lane)*2 + reg   (ks: k16 step in chunk, f: n8 frag)
//   code n = t*128 + f*8 + (lane>>2)
//   k = kc*64 + ks*16 + reg*8 + (lane&3)*2 + h   (h = half within uint)
// Matches the mma.sync m16n8k16 B fragment: main-kernel B loads = one LDS.64.
// ---------------------------------------------------------------------------
__global__ __launch_bounds__(256) void bprep_kernel(const float* __restrict__ cb) {
    int stg = blockIdx.x;
    int t = stg >> 1, kc = stg & 1;
    for (int i = threadIdx.x; i < STG_UINTS; i += 256) {
        int reg  = i & 1;
        int lane = (i >> 1) & 31;
        int f    = (i >> 6) & 15;
        int ks   = (i >> 10) & 3;
        int n  = t * 128 + f * 8 + (lane >> 2);
        int k0 = kc * 64 + ks * 16 + reg * 8 + (lane & 3) * 2;
        __half h0 = __float2half_rn(cb[(size_t)n * DIM + k0]);
        __half h1 = __float2half_rn(cb[(size_t)n * DIM + k0 + 1]);
        g_Bimg[(size_t)stg * STG_UINTS + i] =
            (uint32_t)__half_as_ushort(h0) | ((uint32_t)__half_as_ushort(h1) << 16);
    }
}

// ---------------------------------------------------------------------------
// Main kernel: fp16 approx GEMM + top-2 argmin + flagging.
//   8 warps = 2(m) x 4(n); warp tile 64 rows x 32 codes; 2 CTAs/SM.
// ---------------------------------------------------------------------------
__global__ __launch_bounds__(256, 2)
void vq_main(const float* __restrict__ ze,
             const float* __restrict__ cb,
             float* __restrict__ out) {
    extern __shared__ float sm[];
    const uint32_t sb = smem_u32(sm);
    const int tid  = threadIdx.x;
    const int wid  = tid >> 5;
    const int lane = tid & 31;
    const int wm   = wid & 1;
    const int wn   = wid >> 1;
    const int m0   = blockIdx.x * MT;

    // prime B pipeline: stage 0 -> buffer 0 (4 x 16B per thread)
    {
        const uint32_t* src = g_Bimg + tid * 4;
        uint32_t dst = sb + (BB_OFF + tid * 4) * 4;
        #pragma unroll
        for (int j = 0; j < 4; j++) CP16(dst + j * 4096, src + j * 1024);
        CP_COMMIT();
    }

    for (int i = tid; i < KCB; i += 256) sm[CN_OFF + i] = g_cnorm[i];

    // zh fp16 fragment image build (m16n8k16 A-fragment layout)
    {
        __half* ZHh = (__half*)(sm + ZH_OFF);
        for (int i = tid; i < MT * DIM; i += 256) {
            int m = i >> 7, k = i & 127;
            float v = ze[(size_t)(m0 + m) * DIM + k];
            int ks = k >> 4, kk = k & 15, mf = m >> 4, r = m & 15;
            int lan = ((r & 7) << 2) | ((kk >> 1) & 3);
            int reg = ((kk >> 3) << 1) | (r >> 3);
            int h   = kk & 1;
            ZHh[(((ks * 8 + mf) * 32 + lan) * 4 + reg) * 2 + h] = __float2half_rn(v);
        }
    }

    float acc[4][4][4];
    #pragma unroll
    for (int a = 0; a < 4; a++)
        #pragma unroll
        for (int b = 0; b < 4; b++)
            #pragma unroll
            for (int c = 0; c < 4; c++) acc[a][b][c] = 0.0f;

    float minv[8], minv2[8];
    int   mini[8];
    #pragma unroll
    for (int i = 0; i < 8; i++) { minv[i] = 3.4e38f; minv2[i] = 3.4e38f; mini[i] = 0; }

    const uint4* ZH = (const uint4*)(sm + ZH_OFF);

    for (int st = 0; st < NSTG; st++) {
        if (st < NSTG - 1) {
            const uint32_t* src = g_Bimg + (size_t)(st + 1) * STG_UINTS + tid * 4;
            uint32_t dst = sb + (BB_OFF + ((st + 1) & 1) * STG_UINTS + tid * 4) * 4;
            #pragma unroll
            for (int j = 0; j < 4; j++) CP16(dst + j * 4096, src + j * 1024);
            CP_COMMIT();
            asm volatile("cp.async.wait_group 1;" ::: "memory");
        } else {
            asm volatile("cp.async.wait_group 0;" ::: "memory");
        }
        __syncthreads();

        const uint2* Bp = (const uint2*)(sm + BB_OFF + (st & 1) * STG_UINTS);
        const int kc = st & 1;

        #pragma unroll
        for (int s = 0; s < 4; s++) {
            const int ksg = kc * 4 + s;           // global k16 step 0..7
            uint32_t ah[4][4], bh[4][2];
            #pragma unroll
            for (int mf = 0; mf < 4; mf++) {
                uint4 h = ZH[(ksg * 8 + wm * 4 + mf) * 32 + lane];
                ah[mf][0] = h.x; ah[mf][1] = h.y; ah[mf][2] = h.z; ah[mf][3] = h.w;
            }
            #pragma unroll
            for (int f = 0; f < 4; f++) {
                uint2 h = Bp[(s * 16 + wn * 4 + f) * 32 + lane];
                bh[f][0] = h.x; bh[f][1] = h.y;
            }
            #pragma unroll
            for (int mf = 0; mf < 4; mf++)
                #pragma unroll
                for (int f = 0; f < 4; f++)
                    MMA16(acc[mf][f], ah[mf], bh[f]);
        }

        if (st & 1) {                              // tile t = st>>1 complete
            const int kb = (st >> 1) * 128 + wn * 32 + 2 * (lane & 3);
            #pragma unroll
            for (int mf = 0; mf < 4; mf++)
                #pragma unroll
                for (int f = 0; f < 4; f++)
                    #pragma unroll
                    for (int c = 0; c < 4; c++) {
                        int kn = kb + f * 8 + (c & 1);
                        float sc = fmaf(-2.0f, acc[mf][f][c], sm[CN_OFF + kn]);
                        int i = mf * 2 + (c >> 1);
                        if (sc < minv[i]) {
                            minv2[i] = minv[i]; minv[i] = sc; mini[i] = kn;
                        } else if (sc < minv2[i]) {
                            minv2[i] = sc;
                        }
                        acc[mf][f][c] = 0.0f;
                    }
        }
        __syncthreads();
    }

    // cross-thread top-2 combine (16 partials per row)
    float* rv1  = sm + BB_OFF;                   // [128][16]
    int*   ri1  = (int*)(sm + BB_OFF + 2048);
    float* rv2  = sm + BB_OFF + 4096;
    int*   fidx = (int*)(sm + BB_OFF + 6144);
    #pragma unroll
    for (int i = 0; i < 8; i++) {
        int mfl = i >> 1, rh = i & 1;
        int m = wm * 64 + mfl * 16 + rh * 8 + (lane >> 2);
        int slot = wn * 4 + (lane & 3);
        rv1[m * 16 + slot] = minv[i];
        ri1[m * 16 + slot] = mini[i];
        rv2[m * 16 + slot] = minv2[i];
    }
    __syncthreads();
    if (tid < MT) {
        float m1 = rv1[tid * 16], m2 = rv2[tid * 16];
        int   i1 = ri1[tid * 16];
        #pragma unroll
        for (int t = 1; t < 16; t++) {
            float v1 = rv1[tid * 16 + t], v2 = rv2[tid * 16 + t];
            int  id = ri1[tid * 16 + t];
            if (v1 < m1 || (v1 == m1 && id < i1)) {
                m2 = fminf(m1, v2); m1 = v1; i1 = id;
            } else {
                m2 = fminf(m2, v1);
            }
        }
        fidx[tid] = i1;
        if (m2 - m1 < TAU) {
            int p = atomicAdd(&g_rcnt, 1);
            g_rlist[p] = m0 + tid;
        }
    }
    __syncthreads();

    // gather + write output (rescue overwrites flagged rows later)
    const float4* cb4 = (const float4*)cb;
    float4* out4 = (float4*)out;
    for (int i = tid; i < MT * (DIM / 4); i += 256) {
        int m = i >> 5, c = i & 31;
        out4[(size_t)(m0 + m) * 32 + c] = cb4[(size_t)fidx[m] * 32 + c];
    }
}

// ---------------------------------------------------------------------------
// Rescue v2: exact fp32 full 2048-scan, register-tiled.
//   16 rows/block; 256 threads = 4(ty: 4 rows each) x 64(tx: 2 codes each).
//   z d2-major [64][18] ull (broadcast loads), c d2-major [64][130] ull
//   (conflict-free LDS.128). 3 LDS.128 per 8 FFMA2.
// ---------------------------------------------------------------------------
#define RPB 16
// smem float offsets
#define RS_Z   0                          // 64*18 ull  = 2304 floats
#define RS_C   2304                       // 64*130 ull = 16640 floats
#define RS_N   18944                      // 128 norms
#define RS_V   19072                      // [16 rows][64 slots]
#define RS_I   20096
#define RS_L   21120                      // 16 list entries
#define RS_FLOATS 21136
#define RS_BYTES  (RS_FLOATS * 4)

__global__ __launch_bounds__(256, 2)
void rescue_kernel(const float* __restrict__ ze,
                   const float* __restrict__ cb,
                   float* __restrict__ out) {
    const int base = blockIdx.x * RPB;
    const int cnt = g_rcnt;
    if (base >= cnt) return;
    const int nrows = min(RPB, cnt - base);

    extern __shared__ float rs[];
    unsigned long long* zt = (unsigned long long*)(rs + RS_Z);
    unsigned long long* ct = (unsigned long long*)(rs + RS_C);
    float* rn  = rs + RS_N;
    float* rbv = rs + RS_V;
    int*   rbk = (int*)(rs + RS_I);
    int*   lst = (int*)(rs + RS_L);

    const int tid = threadIdx.x;
    const int ty = tid >> 6;              // 0..3 (rows ty*4..+3)
    const int tx = tid & 63;              // codes tx*2, tx*2+1

    if (tid < RPB)
        lst[tid] = g_rlist[base + ((tid < nrows) ? tid : 0)];
    __syncthreads();

    // z rows -> d2-major smem (float idx = d2*36 + rr*2 + (d&1))
    for (int i = tid; i < RPB * DIM; i += 256) {
        int rr = i >> 7, d = i & 127;
        rs[RS_Z + (d >> 1) * 36 + rr * 2 + (d & 1)] =
            ze[(size_t)lst[rr] * DIM + d];
    }

    float bv[4];
    int   bk[4];
    #pragma unroll
    for (int r = 0; r < 4; r++) { bv[r] = 3.4e38f; bk[r] = 0; }

    for (int t = 0; t < KCB / 128; t++) {
        __syncthreads();
        for (int i = tid; i < 128 * DIM; i += 256) {
            int c = i >> 7, d = i & 127;
            rs[RS_C + (d >> 1) * 260 + c * 2 + (d & 1)] =
                cb[(size_t)(t * 128 + c) * DIM + d];
        }
        if (tid < 128) rn[tid] = g_cnorm[t * 128 + tid];
        __syncthreads();

        unsigned long long a0 = 0, a1 = 0, a2 = 0, a3 = 0;
        unsigned long long b0 = 0, b1 = 0, b2 = 0, b3 = 0;
        unsigned long long c0 = 0, c1 = 0;
        (void)b0; (void)b1; (void)b2; (void)b3;
        unsigned long long acc8[4][2];
        #pragma unroll
        for (int r = 0; r < 4; r++) { acc8[r][0] = 0; acc8[r][1] = 0; }

        const ulonglong2* ZA = (const ulonglong2*)(zt) ;
        const ulonglong2* CA = (const ulonglong2*)(ct);
        #pragma unroll 4
        for (int d2 = 0; d2 < 64; d2++) {
            ulonglong2 za0 = ZA[(d2 * 18 + ty * 4) >> 1];
            ulonglong2 za1 = ZA[(d2 * 18 + ty * 4 + 2) >> 1];
            ulonglong2 cb2 = CA[(d2 * 130 + tx * 2) >> 1];
            a0 = za0.x; a1 = za0.y; a2 = za1.x; a3 = za1.y;
            c0 = cb2.x; c1 = cb2.y;
            fma_f32x2(acc8[0][0], a0, c0); fma_f32x2(acc8[0][1], a0, c1);
            fma_f32x2(acc8[1][0], a1, c0); fma_f32x2(acc8[1][1], a1, c1);
            fma_f32x2(acc8[2][0], a2, c0); fma_f32x2(acc8[2][1], a2, c1);
            fma_f32x2(acc8[3][0], a3, c0); fma_f32x2(acc8[3][1], a3, c1);
        }
        #pragma unroll
        for (int r = 0; r < 4; r++)
            #pragma unroll
            for (int cc = 0; cc < 2; cc++) {
                int kg = t * 128 + tx * 2 + cc;
                float s = fmaf(-2.0f, pair_sum(acc8[r][cc]), rn[tx * 2 + cc]);
                if (s < bv[r] || (s == bv[r] && kg < bk[r])) {
                    bv[r] = s; bk[r] = kg;
                }
            }
    }
    __syncthreads();
    #pragma unroll
    for (int r = 0; r < 4; r++) {
        int row = ty * 4 + r;
        rbv[row * 64 + tx] = bv[r];
        rbk[row * 64 + tx] = bk[r];
    }
    __syncthreads();

    if (tid < RPB) {
        float m1 = rbv[tid * 64];
        int   i1 = rbk[tid * 64];
        for (int s = 1; s < 64; s++) {
            float v = rbv[tid * 64 + s];
            int  id = rbk[tid * 64 + s];
            if (v < m1 || (v == m1 && id < i1)) { m1 = v; i1 = id; }
        }
        rbk[tid * 64] = i1;
    }
    __syncthreads();

    for (int i = tid; i < nrows * DIM; i += 256) {
        int rr = i >> 7, d = i & 127;
        out[(size_t)lst[rr] * DIM + d] = cb[(size_t)rbk[rr * 64] * DIM + d];
    }
}

// ---------------------------------------------------------------------------
extern "C" void kernel_launch(void* const* d_in, const int* in_sizes, int n_in,
                              void* d_out, int out_size) {
    const float* ze = (const float*)d_in[0];   // [65536, 128]
    const float* cb = (const float*)d_in[1];   // [2048, 128]
    float* out = (float*)d_out;
    (void)in_sizes; (void)n_in; (void)out_size;

    cudaFuncSetAttribute(vq_main,
                         cudaFuncAttributeMaxDynamicSharedMemorySize, SMEM_BYTES);
    cudaFuncSetAttribute(rescue_kernel,
                         cudaFuncAttributeMaxDynamicSharedMemorySize, RS_BYTES);

    cnorm_kernel<<<KCB / 8, 256>>>(cb);
    bprep_kernel<<<NSTG, 256>>>(cb);
    vq_main<<<NWIN / MT, 256, SMEM_BYTES>>>(ze, cb, out);
    rescue_kernel<<<NWIN / RPB, 256, RS_BYTES>>>(ze, cb, out);
}

// round 8
// speedup vs baseline: 2.6058x; 1.1915x over previous
#include <cuda_runtime.h>
#include <cuda_fp16.h>
#include <cstdint>

// ---------------------------------------------------------------------------
// Problem constants
// ---------------------------------------------------------------------------
#define NWIN   65536
#define DIM    128
#define KCB    2048
#define MT     128              // windows per CTA
#define NSTG   32               // stages: (tile, k64-chunk)
#define STG_UINTS 4096          // one stage = 16 KB fp16 frag image

// main-kernel smem layout (float offsets)
#define ZH_OFF   0              // zh fp16 frag image
#define BB_OFF   8192           // B double buffer: 2 x 4096 uints
#define CN_OFF   16384          // 2048 codebook norms
#define SMEM_FLOATS 18432
#define SMEM_BYTES  (SMEM_FLOATS * 4)

#define TAU 0.18f               // rescue threshold on approx min2-min1 gap

__device__ float    g_cnorm[KCB];
__device__ uint32_t g_Bimg[NSTG * STG_UINTS];   // 512 KB fp16 fragment image
__device__ int      g_rcnt;
__device__ int      g_rlist[NWIN];
__device__ unsigned long long g_rbest[NWIN];    // packed (score-key<<32)|idx

// ---------------------------------------------------------------------------
// Helpers
// ---------------------------------------------------------------------------
__device__ __forceinline__ uint32_t smem_u32(const void* p) {
    uint32_t a;
    asm("{ .reg .u64 t; cvta.to.shared.u64 t, %1; cvt.u32.u64 %0, t; }"
        : "=r"(a) : "l"(p));
    return a;
}
__device__ __forceinline__ void fma_f32x2(unsigned long long& acc,
                                          unsigned long long a,
                                          unsigned long long b) {
    asm("fma.rn.f32x2 %0, %1, %2, %0;" : "+l"(acc) : "l"(a), "l"(b));
}
__device__ __forceinline__ float pair_sum(unsigned long long p) {
    return __uint_as_float((unsigned)(p & 0xFFFFFFFFull))
         + __uint_as_float((unsigned)(p >> 32));
}
// monotone float -> sortable u32 (ascending float == ascending uint)
__device__ __forceinline__ uint32_t fkey(float s) {
    uint32_t b = __float_as_uint(s);
    return b ^ ((uint32_t)((int32_t)b >> 31) | 0x80000000u);
}

// m16n8k16 fp16 MMA, fp32 accum: D += A*B
#define MMA16(d, a, b) \
    asm volatile("mma.sync.aligned.m16n8k16.row.col.f32.f16.f16.f32 " \
        "{%0,%1,%2,%3},{%4,%5,%6,%7},{%8,%9},{%0,%1,%2,%3};" \
        : "+f"((d)[0]), "+f"((d)[1]), "+f"((d)[2]), "+f"((d)[3]) \
        : "r"((a)[0]), "r"((a)[1]), "r"((a)[2]), "r"((a)[3]), \
          "r"((b)[0]), "r"((b)[1]))

#define CP16(dst, src) \
    asm volatile("cp.async.cg.shared.global [%0], [%1], 16;" \
                 :: "r"(dst), "l"(src) : "memory")
#define CP_COMMIT() asm volatile("cp.async.commit_group;" ::: "memory")

// ---------------------------------------------------------------------------
// Prep 1: codebook squared norms (exact fp32); zero rescue counter.
// ---------------------------------------------------------------------------
__global__ void cnorm_kernel(const float* __restrict__ cb) {
    if (blockIdx.x == 0 && threadIdx.x == 0) g_rcnt = 0;
    int warp = (blockIdx.x * blockDim.x + threadIdx.x) >> 5;
    int lane = threadIdx.x & 31;
    if (warp >= KCB) return;
    const float4* row = (const float4*)(cb + (size_t)warp * DIM);
    float4 v = row[lane];
    float s = v.x * v.x + v.y * v.y + v.z * v.z + v.w * v.w;
    #pragma unroll
    for (int o = 16; o; o >>= 1) s += __shfl_xor_sync(0xFFFFFFFFu, s, o);
    if (lane == 0) g_cnorm[warp] = s;
}

// ---------------------------------------------------------------------------
// Prep 2: fragment-major fp16 B image (m16n8k16 B-fragment layout).
// ---------------------------------------------------------------------------
__global__ __launch_bounds__(256) void bprep_kernel(const float* __restrict__ cb) {
    int stg = blockIdx.x;
    int t = stg >> 1, kc = stg & 1;
    for (int i = threadIdx.x; i < STG_UINTS; i += 256) {
        int reg  = i & 1;
        int lane = (i >> 1) & 31;
        int f    = (i >> 6) & 15;
        int ks   = (i >> 10) & 3;
        int n  = t * 128 + f * 8 + (lane >> 2);
        int k0 = kc * 64 + ks * 16 + reg * 8 + (lane & 3) * 2;
        __half h0 = __float2half_rn(cb[(size_t)n * DIM + k0]);
        __half h1 = __float2half_rn(cb[(size_t)n * DIM + k0 + 1]);
        g_Bimg[(size_t)stg * STG_UINTS + i] =
            (uint32_t)__half_as_ushort(h0) | ((uint32_t)__half_as_ushort(h1) << 16);
    }
}

// ---------------------------------------------------------------------------
// Main kernel: fp16 approx GEMM + top-2 argmin + flagging. (unchanged fast path)
// ---------------------------------------------------------------------------
__global__ __launch_bounds__(256, 2)
void vq_main(const float* __restrict__ ze,
             const float* __restrict__ cb,
             float* __restrict__ out) {
    extern __shared__ float sm[];
    const uint32_t sb = smem_u32(sm);
    const int tid  = threadIdx.x;
    const int wid  = tid >> 5;
    const int lane = tid & 31;
    const int wm   = wid & 1;
    const int wn   = wid >> 1;
    const int m0   = blockIdx.x * MT;

    {
        const uint32_t* src = g_Bimg + tid * 4;
        uint32_t dst = sb + (BB_OFF + tid * 4) * 4;
        #pragma unroll
        for (int j = 0; j < 4; j++) CP16(dst + j * 4096, src + j * 1024);
        CP_COMMIT();
    }

    for (int i = tid; i < KCB; i += 256) sm[CN_OFF + i] = g_cnorm[i];

    {
        __half* ZHh = (__half*)(sm + ZH_OFF);
        for (int i = tid; i < MT * DIM; i += 256) {
            int m = i >> 7, k = i & 127;
            float v = ze[(size_t)(m0 + m) * DIM + k];
            int ks = k >> 4, kk = k & 15, mf = m >> 4, r = m & 15;
            int lan = ((r & 7) << 2) | ((kk >> 1) & 3);
            int reg = ((kk >> 3) << 1) | (r >> 3);
            int h   = kk & 1;
            ZHh[(((ks * 8 + mf) * 32 + lan) * 4 + reg) * 2 + h] = __float2half_rn(v);
        }
    }

    float acc[4][4][4];
    #pragma unroll
    for (int a = 0; a < 4; a++)
        #pragma unroll
        for (int b = 0; b < 4; b++)
            #pragma unroll
            for (int c = 0; c < 4; c++) acc[a][b][c] = 0.0f;

    float minv[8], minv2[8];
    int   mini[8];
    #pragma unroll
    for (int i = 0; i < 8; i++) { minv[i] = 3.4e38f; minv2[i] = 3.4e38f; mini[i] = 0; }

    const uint4* ZH = (const uint4*)(sm + ZH_OFF);

    for (int st = 0; st < NSTG; st++) {
        if (st < NSTG - 1) {
            const uint32_t* src = g_Bimg + (size_t)(st + 1) * STG_UINTS + tid * 4;
            uint32_t dst = sb + (BB_OFF + ((st + 1) & 1) * STG_UINTS + tid * 4) * 4;
            #pragma unroll
            for (int j = 0; j < 4; j++) CP16(dst + j * 4096, src + j * 1024);
            CP_COMMIT();
            asm volatile("cp.async.wait_group 1;" ::: "memory");
        } else {
            asm volatile("cp.async.wait_group 0;" ::: "memory");
        }
        __syncthreads();

        const uint2* Bp = (const uint2*)(sm + BB_OFF + (st & 1) * STG_UINTS);
        const int kc = st & 1;

        #pragma unroll
        for (int s = 0; s < 4; s++) {
            const int ksg = kc * 4 + s;
            uint32_t ah[4][4], bh[4][2];
            #pragma unroll
            for (int mf = 0; mf < 4; mf++) {
                uint4 h = ZH[(ksg * 8 + wm * 4 + mf) * 32 + lane];
                ah[mf][0] = h.x; ah[mf][1] = h.y; ah[mf][2] = h.z; ah[mf][3] = h.w;
            }
            #pragma unroll
            for (int f = 0; f < 4; f++) {
                uint2 h = Bp[(s * 16 + wn * 4 + f) * 32 + lane];
                bh[f][0] = h.x; bh[f][1] = h.y;
            }
            #pragma unroll
            for (int mf = 0; mf < 4; mf++)
                #pragma unroll
                for (int f = 0; f < 4; f++)
                    MMA16(acc[mf][f], ah[mf], bh[f]);
        }

        if (st & 1) {
            const int kb = (st >> 1) * 128 + wn * 32 + 2 * (lane & 3);
            #pragma unroll
            for (int mf = 0; mf < 4; mf++)
                #pragma unroll
                for (int f = 0; f < 4; f++)
                    #pragma unroll
                    for (int c = 0; c < 4; c++) {
                        int kn = kb + f * 8 + (c & 1);
                        float sc = fmaf(-2.0f, acc[mf][f][c], sm[CN_OFF + kn]);
                        int i = mf * 2 + (c >> 1);
                        if (sc < minv[i]) {
                            minv2[i] = minv[i]; minv[i] = sc; mini[i] = kn;
                        } else if (sc < minv2[i]) {
                            minv2[i] = sc;
                        }
                        acc[mf][f][c] = 0.0f;
                    }
        }
        __syncthreads();
    }

    float* rv1  = sm + BB_OFF;
    int*   ri1  = (int*)(sm + BB_OFF + 2048);
    float* rv2  = sm + BB_OFF + 4096;
    int*   fidx = (int*)(sm + BB_OFF + 6144);
    #pragma unroll
    for (int i = 0; i < 8; i++) {
        int mfl = i >> 1, rh = i & 1;
        int m = wm * 64 + mfl * 16 + rh * 8 + (lane >> 2);
        int slot = wn * 4 + (lane & 3);
        rv1[m * 16 + slot] = minv[i];
        ri1[m * 16 + slot] = mini[i];
        rv2[m * 16 + slot] = minv2[i];
    }
    __syncthreads();
    if (tid < MT) {
        float m1 = rv1[tid * 16], m2 = rv2[tid * 16];
        int   i1 = ri1[tid * 16];
        #pragma unroll
        for (int t = 1; t < 16; t++) {
            float v1 = rv1[tid * 16 + t], v2 = rv2[tid * 16 + t];
            int  id = ri1[tid * 16 + t];
            if (v1 < m1 || (v1 == m1 && id < i1)) {
                m2 = fminf(m1, v2); m1 = v1; i1 = id;
            } else {
                m2 = fminf(m2, v1);
            }
        }
        fidx[tid] = i1;
        if (m2 - m1 < TAU) {
            g_rbest[m0 + tid] = ~0ull;         // init merge slot
            int p = atomicAdd(&g_rcnt, 1);
            g_rlist[p] = m0 + tid;
        }
    }
    __syncthreads();

    const float4* cb4 = (const float4*)cb;
    float4* out4 = (float4*)out;
    for (int i = tid; i < MT * (DIM / 4); i += 256) {
        int m = i >> 5, c = i & 31;
        out4[(size_t)(m0 + m) * 32 + c] = cb4[(size_t)fidx[m] * 32 + c];
    }
}

// ---------------------------------------------------------------------------
// Rescue scan: exact fp32, k-split. Block (bx, kt): 128 gathered rows x
// codebook tile kt (128 codes). R1-style 8x8 f32x2 register tiling, then
// per-row atomicMin merge of packed (score-key, idx) into g_rbest.
// ---------------------------------------------------------------------------
#define RS2_LST  (2 * 64 * 128)               // ull offset of row list
#define RS2_BYTES (2 * 64 * 128 * 8 + 512 + 64)

__global__ __launch_bounds__(256, 1)
void rescue_scan(const float* __restrict__ ze,
                 const float* __restrict__ cb) {
    const int cnt = g_rcnt;
    const int base = blockIdx.x * 128;
    if (base >= cnt) return;

    extern __shared__ unsigned long long rsm[];
    unsigned long long* zs = rsm;             // [64][128] (d2, row)
    unsigned long long* cs = rsm + 64 * 128;  // [64][128] (d2, code)
    int* lst = (int*)(rsm + RS2_LST);         // 128 gathered row ids

    const int tid = threadIdx.x;
    const int tx  = tid & 15;
    const int ty  = tid >> 4;
    const int kt  = blockIdx.y;

    if (tid < 128) {
        int p = base + tid;
        lst[tid] = g_rlist[p < cnt ? p : base];   // pad with dup of first
    }
    __syncthreads();

    // gather z rows (transposed, d2-major)
    for (int i = tid; i < 128 * 64; i += 256) {
        int m = i >> 6, d2 = i & 63;
        zs[d2 * 128 + m] =
            ((const unsigned long long*)(ze + (size_t)lst[m] * DIM))[d2];
    }
    // codebook tile kt (transposed)
    {
        const unsigned long long* cg =
            (const unsigned long long*)(cb + (size_t)kt * 128 * DIM);
        for (int i = tid; i < 128 * 64; i += 256) {
            int k = i >> 6, d2 = i & 63;
            cs[d2 * 128 + k] = cg[i];
        }
    }
    __syncthreads();

    unsigned long long acc[8][8];
    #pragma unroll
    for (int i = 0; i < 8; i++)
        #pragma unroll
        for (int j = 0; j < 8; j++) acc[i][j] = 0ull;

    #pragma unroll 2
    for (int d2 = 0; d2 < 64; d2++) {
        unsigned long long a[8], b[8];
        const ulonglong2* za = (const ulonglong2*)(zs + d2 * 128 + ty * 8);
        const ulonglong2* cbase = (const ulonglong2*)(cs + d2 * 128);
        #pragma unroll
        for (int c = 0; c < 4; c++) {
            ulonglong2 av = za[c];
            a[2 * c] = av.x; a[2 * c + 1] = av.y;
            ulonglong2 bv = cbase[tx + 16 * c];
            b[2 * c] = bv.x; b[2 * c + 1] = bv.y;
        }
        #pragma unroll
        for (int i = 0; i < 8; i++)
            #pragma unroll
            for (int j = 0; j < 8; j++)
                fma_f32x2(acc[i][j], a[i], b[j]);
    }

    float minv[8];
    int   mini[8];
    #pragma unroll
    for (int i = 0; i < 8; i++) { minv[i] = 3.4e38f; mini[i] = 0; }

    #pragma unroll
    for (int j = 0; j < 8; j++) {
        int kg = kt * 128 + 32 * (j >> 1) + 2 * tx + (j & 1);
        float cn = g_cnorm[kg];
        #pragma unroll
        for (int i = 0; i < 8; i++) {
            float s = fmaf(-2.0f, pair_sum(acc[i][j]), cn);
            if (s < minv[i]) { minv[i] = s; mini[i] = kg; }
        }
    }

    // cross-thread reduce (16 tx partials per row), then atomic merge
    __syncthreads();
    float* rv = (float*)cs;                   // [16][132]
    int*   ri = (int*)(rv + 16 * 132);
    #pragma unroll
    for (int i = 0; i < 8; i++) {
        int m = ty * 8 + i;
        rv[tx * 132 + m] = minv[i];
        ri[tx * 132 + m] = mini[i];
    }
    __syncthreads();
    if (tid < 128) {
        float bv = rv[tid];
        int   bi = ri[tid];
        #pragma unroll
        for (int t = 1; t < 16; t++) {
            float v = rv[t * 132 + tid];
            int  id = ri[t * 132 + tid];
            if (v < bv || (v == bv && id < bi)) { bv = v; bi = id; }
        }
        unsigned long long packed =
            ((unsigned long long)fkey(bv) << 32) | (uint32_t)bi;
        atomicMin(&g_rbest[lst[tid]], packed);
    }
}

// ---------------------------------------------------------------------------
// Rescue write: overwrite flagged rows with the exact winner's codeword.
// ---------------------------------------------------------------------------
__global__ __launch_bounds__(256, 4)
void rescue_write(const float* __restrict__ cb, float* __restrict__ out) {
    const int cnt = g_rcnt;
    const int base = blockIdx.x * 32;
    if (base >= cnt) return;
    const int tid = threadIdx.x;
    const float4* cb4 = (const float4*)cb;
    float4* out4 = (float4*)out;
    for (int i = tid; i < 32 * 32; i += 256) {
        int r = base + (i >> 5), c = i & 31;
        if (r < cnt) {
            int row = g_rlist[r];
            uint32_t idx = (uint32_t)(g_rbest[row] & 0xFFFFFFFFull);
            out4[(size_t)row * 32 + c] = cb4[(size_t)idx * 32 + c];
        }
    }
}

// ---------------------------------------------------------------------------
extern "C" void kernel_launch(void* const* d_in, const int* in_sizes, int n_in,
                              void* d_out, int out_size) {
    const float* ze = (const float*)d_in[0];   // [65536, 128]
    const float* cb = (const float*)d_in[1];   // [2048, 128]
    float* out = (float*)d_out;
    (void)in_sizes; (void)n_in; (void)out_size;

    cudaFuncSetAttribute(vq_main,
                         cudaFuncAttributeMaxDynamicSharedMemorySize, SMEM_BYTES);
    cudaFuncSetAttribute(rescue_scan,
                         cudaFuncAttributeMaxDynamicSharedMemorySize, RS2_BYTES);

    cnorm_kernel<<<KCB / 8, 256>>>(cb);
    bprep_kernel<<<NSTG, 256>>>(cb);
    vq_main<<<NWIN / MT, 256, SMEM_BYTES>>>(ze, cb, out);
    rescue_scan<<<dim3(NWIN / 128, KCB / 128), 256, RS2_BYTES>>>(ze, cb);
    rescue_write<<<NWIN / 32, 256>>>(cb, out);
}

// round 9
// speedup vs baseline: 2.7742x; 1.0646x over previous
#include <cuda_runtime.h>
#include <cuda_fp16.h>
#include <cstdint>

// ---------------------------------------------------------------------------
// Problem constants
// ---------------------------------------------------------------------------
#define NWIN   65536
#define DIM    128
#define KCB    2048
#define MT     128              // windows per CTA
#define NSTG   32               // stages: (tile, k64-chunk)
#define STG_UINTS 4096          // one stage = 16 KB fp16 frag image

// main-kernel smem layout (float offsets)
#define ZH_OFF   0              // zh fp16 frag image
#define BB_OFF   8192           // B double buffer: 2 x 4096 uints
#define CN_OFF   16384          // 2048 codebook norms
#define SMEM_FLOATS 18432
#define SMEM_BYTES  (SMEM_FLOATS * 4)

#define TAU 0.18f               // rescue threshold on approx min2-min1 gap

__device__ float    g_cnorm[KCB];
__device__ uint32_t g_Bimg[NSTG * STG_UINTS];   // 512 KB fp16 fragment image
__device__ int      g_rcnt;
__device__ int      g_rlist[NWIN];
__device__ unsigned long long g_rbest[NWIN];    // packed (score-key<<32)|idx

// ---------------------------------------------------------------------------
// Helpers
// ---------------------------------------------------------------------------
__device__ __forceinline__ uint32_t smem_u32(const void* p) {
    uint32_t a;
    asm("{ .reg .u64 t; cvta.to.shared.u64 t, %1; cvt.u32.u64 %0, t; }"
        : "=r"(a) : "l"(p));
    return a;
}
__device__ __forceinline__ void fma_f32x2(unsigned long long& acc,
                                          unsigned long long a,
                                          unsigned long long b) {
    asm("fma.rn.f32x2 %0, %1, %2, %0;" : "+l"(acc) : "l"(a), "l"(b));
}
__device__ __forceinline__ float pair_sum(unsigned long long p) {
    return __uint_as_float((unsigned)(p & 0xFFFFFFFFull))
         + __uint_as_float((unsigned)(p >> 32));
}
// monotone float -> sortable u32 (ascending float == ascending uint)
__device__ __forceinline__ uint32_t fkey(float s) {
    uint32_t b = __float_as_uint(s);
    return b ^ ((uint32_t)((int32_t)b >> 31) | 0x80000000u);
}

// m16n8k16 fp16 MMA, fp32 accum: D += A*B
#define MMA16(d, a, b) \
    asm volatile("mma.sync.aligned.m16n8k16.row.col.f32.f16.f16.f32 " \
        "{%0,%1,%2,%3},{%4,%5,%6,%7},{%8,%9},{%0,%1,%2,%3};" \
        : "+f"((d)[0]), "+f"((d)[1]), "+f"((d)[2]), "+f"((d)[3]) \
        : "r"((a)[0]), "r"((a)[1]), "r"((a)[2]), "r"((a)[3]), \
          "r"((b)[0]), "r"((b)[1]))

#define CP16(dst, src) \
    asm volatile("cp.async.cg.shared.global [%0], [%1], 16;" \
                 :: "r"(dst), "l"(src) : "memory")
#define CP_COMMIT() asm volatile("cp.async.commit_group;" ::: "memory")

// ---------------------------------------------------------------------------
// Merged prep: blocks 0..127 build the fp16 B fragment image (quarter-stage
// each); blocks 128..135 compute codebook norms (1 thread per row).
// ---------------------------------------------------------------------------
__global__ __launch_bounds__(256) void prep_kernel(const float* __restrict__ cb) {
    const int b = blockIdx.x;
    if (b < 128) {
        const int stg = b >> 2;
        const int q   = b & 3;
        const int t = stg >> 1, kc = stg & 1;
        for (int ii = threadIdx.x; ii < 1024; ii += 256) {
            int i = q * 1024 + ii;
            int reg  = i & 1;
            int lane = (i >> 1) & 31;
            int f    = (i >> 6) & 15;
            int ks   = (i >> 10) & 3;
            int n  = t * 128 + f * 8 + (lane >> 2);
            int k0 = kc * 64 + ks * 16 + reg * 8 + (lane & 3) * 2;
            __half h0 = __float2half_rn(cb[(size_t)n * DIM + k0]);
            __half h1 = __float2half_rn(cb[(size_t)n * DIM + k0 + 1]);
            g_Bimg[(size_t)stg * STG_UINTS + i] =
                (uint32_t)__half_as_ushort(h0)
                | ((uint32_t)__half_as_ushort(h1) << 16);
        }
    } else {
        if (b == 128 && threadIdx.x == 0) g_rcnt = 0;
        int row = (b - 128) * 256 + threadIdx.x;   // 8 blocks x 256 = 2048 rows
        const float4* r4 = (const float4*)(cb + (size_t)row * DIM);
        float s = 0.0f;
        #pragma unroll 8
        for (int j = 0; j < 32; j++) {
            float4 v = r4[j];
            s += v.x * v.x + v.y * v.y + v.z * v.z + v.w * v.w;
        }
        g_cnorm[row] = s;
    }
}

// ---------------------------------------------------------------------------
// Main kernel: fp16 approx GEMM + top-2 argmin + flagging. (unchanged fast path)
// ---------------------------------------------------------------------------
__global__ __launch_bounds__(256, 2)
void vq_main(const float* __restrict__ ze,
             const float* __restrict__ cb,
             float* __restrict__ out) {
    extern __shared__ float sm[];
    const uint32_t sb = smem_u32(sm);
    const int tid  = threadIdx.x;
    const int wid  = tid >> 5;
    const int lane = tid & 31;
    const int wm   = wid & 1;
    const int wn   = wid >> 1;
    const int m0   = blockIdx.x * MT;

    {
        const uint32_t* src = g_Bimg + tid * 4;
        uint32_t dst = sb + (BB_OFF + tid * 4) * 4;
        #pragma unroll
        for (int j = 0; j < 4; j++) CP16(dst + j * 4096, src + j * 1024);
        CP_COMMIT();
    }

    for (int i = tid; i < KCB; i += 256) sm[CN_OFF + i] = g_cnorm[i];

    {
        __half* ZHh = (__half*)(sm + ZH_OFF);
        for (int i = tid; i < MT * DIM; i += 256) {
            int m = i >> 7, k = i & 127;
            float v = ze[(size_t)(m0 + m) * DIM + k];
            int ks = k >> 4, kk = k & 15, mf = m >> 4, r = m & 15;
            int lan = ((r & 7) << 2) | ((kk >> 1) & 3);
            int reg = ((kk >> 3) << 1) | (r >> 3);
            int h   = kk & 1;
            ZHh[(((ks * 8 + mf) * 32 + lan) * 4 + reg) * 2 + h] = __float2half_rn(v);
        }
    }

    float acc[4][4][4];
    #pragma unroll
    for (int a = 0; a < 4; a++)
        #pragma unroll
        for (int b = 0; b < 4; b++)
            #pragma unroll
            for (int c = 0; c < 4; c++) acc[a][b][c] = 0.0f;

    float minv[8], minv2[8];
    int   mini[8];
    #pragma unroll
    for (int i = 0; i < 8; i++) { minv[i] = 3.4e38f; minv2[i] = 3.4e38f; mini[i] = 0; }

    const uint4* ZH = (const uint4*)(sm + ZH_OFF);

    for (int st = 0; st < NSTG; st++) {
        if (st < NSTG - 1) {
            const uint32_t* src = g_Bimg + (size_t)(st + 1) * STG_UINTS + tid * 4;
            uint32_t dst = sb + (BB_OFF + ((st + 1) & 1) * STG_UINTS + tid * 4) * 4;
            #pragma unroll
            for (int j = 0; j < 4; j++) CP16(dst + j * 4096, src + j * 1024);
            CP_COMMIT();
            asm volatile("cp.async.wait_group 1;" ::: "memory");
        } else {
            asm volatile("cp.async.wait_group 0;" ::: "memory");
        }
        __syncthreads();

        const uint2* Bp = (const uint2*)(sm + BB_OFF + (st & 1) * STG_UINTS);
        const int kc = st & 1;

        #pragma unroll
        for (int s = 0; s < 4; s++) {
            const int ksg = kc * 4 + s;
            uint32_t ah[4][4], bh[4][2];
            #pragma unroll
            for (int mf = 0; mf < 4; mf++) {
                uint4 h = ZH[(ksg * 8 + wm * 4 + mf) * 32 + lane];
                ah[mf][0] = h.x; ah[mf][1] = h.y; ah[mf][2] = h.z; ah[mf][3] = h.w;
            }
            #pragma unroll
            for (int f = 0; f < 4; f++) {
                uint2 h = Bp[(s * 16 + wn * 4 + f) * 32 + lane];
                bh[f][0] = h.x; bh[f][1] = h.y;
            }
            #pragma unroll
            for (int mf = 0; mf < 4; mf++)
                #pragma unroll
                for (int f = 0; f < 4; f++)
                    MMA16(acc[mf][f], ah[mf], bh[f]);
        }

        if (st & 1) {
            const int kb = (st >> 1) * 128 + wn * 32 + 2 * (lane & 3);
            #pragma unroll
            for (int mf = 0; mf < 4; mf++)
                #pragma unroll
                for (int f = 0; f < 4; f++)
                    #pragma unroll
                    for (int c = 0; c < 4; c++) {
                        int kn = kb + f * 8 + (c & 1);
                        float sc = fmaf(-2.0f, acc[mf][f][c], sm[CN_OFF + kn]);
                        int i = mf * 2 + (c >> 1);
                        if (sc < minv[i]) {
                            minv2[i] = minv[i]; minv[i] = sc; mini[i] = kn;
                        } else if (sc < minv2[i]) {
                            minv2[i] = sc;
                        }
                        acc[mf][f][c] = 0.0f;
                    }
        }
        __syncthreads();
    }

    float* rv1  = sm + BB_OFF;
    int*   ri1  = (int*)(sm + BB_OFF + 2048);
    float* rv2  = sm + BB_OFF + 4096;
    int*   fidx = (int*)(sm + BB_OFF + 6144);
    #pragma unroll
    for (int i = 0; i < 8; i++) {
        int mfl = i >> 1, rh = i & 1;
        int m = wm * 64 + mfl * 16 + rh * 8 + (lane >> 2);
        int slot = wn * 4 + (lane & 3);
        rv1[m * 16 + slot] = minv[i];
        ri1[m * 16 + slot] = mini[i];
        rv2[m * 16 + slot] = minv2[i];
    }
    __syncthreads();
    if (tid < MT) {
        float m1 = rv1[tid * 16], m2 = rv2[tid * 16];
        int   i1 = ri1[tid * 16];
        #pragma unroll
        for (int t = 1; t < 16; t++) {
            float v1 = rv1[tid * 16 + t], v2 = rv2[tid * 16 + t];
            int  id = ri1[tid * 16 + t];
            if (v1 < m1 || (v1 == m1 && id < i1)) {
                m2 = fminf(m1, v2); m1 = v1; i1 = id;
            } else {
                m2 = fminf(m2, v1);
            }
        }
        fidx[tid] = i1;
        if (m2 - m1 < TAU) {
            g_rbest[m0 + tid] = ~0ull;         // init merge slot
            int p = atomicAdd(&g_rcnt, 1);
            g_rlist[p] = m0 + tid;
        }
    }
    __syncthreads();

    const float4* cb4 = (const float4*)cb;
    float4* out4 = (float4*)out;
    for (int i = tid; i < MT * (DIM / 4); i += 256) {
        int m = i >> 5, c = i & 31;
        out4[(size_t)(m0 + m) * 32 + c] = cb4[(size_t)fidx[m] * 32 + c];
    }
}

// ---------------------------------------------------------------------------
// Rescue scan (persistent): exact fp32, k-split. Work item = (row-block bx,
// k-tile kt). 148 blocks loop over items; per item: 128 gathered rows x 128
// codes, 8x8 f32x2 register tiling, atomicMin merge of (score-key, idx).
// ---------------------------------------------------------------------------
#define RS2_LST  (2 * 64 * 128)               // ull offset of row list
#define RS2_BYTES (2 * 64 * 128 * 8 + 512 + 64)
#define RGRID 148

__global__ __launch_bounds__(256, 1)
void rescue_scan(const float* __restrict__ ze,
                 const float* __restrict__ cb) {
    const int cnt = g_rcnt;
    const int nbx = (cnt + 127) >> 7;
    const int total = nbx * 16;

    extern __shared__ unsigned long long rsm[];
    unsigned long long* zs = rsm;             // [64][128] (d2, row)
    unsigned long long* cs = rsm + 64 * 128;  // [64][128] (d2, code)
    int* lst = (int*)(rsm + RS2_LST);

    const int tid = threadIdx.x;
    const int tx  = tid & 15;
    const int ty  = tid >> 4;

    for (int item = blockIdx.x; item < total; item += RGRID) {
        const int bx = item >> 4;
        const int kt = item & 15;
        const int base = bx * 128;

        if (tid < 128) {
            int p = base + tid;
            lst[tid] = g_rlist[p < cnt ? p : base];
        }
        __syncthreads();

        for (int i = tid; i < 128 * 64; i += 256) {
            int m = i >> 6, d2 = i & 63;
            zs[d2 * 128 + m] =
                ((const unsigned long long*)(ze + (size_t)lst[m] * DIM))[d2];
        }
        {
            const unsigned long long* cg =
                (const unsigned long long*)(cb + (size_t)kt * 128 * DIM);
            for (int i = tid; i < 128 * 64; i += 256) {
                int k = i >> 6, d2 = i & 63;
                cs[d2 * 128 + k] = cg[i];
            }
        }
        __syncthreads();

        unsigned long long acc[8][8];
        #pragma unroll
        for (int i = 0; i < 8; i++)
            #pragma unroll
            for (int j = 0; j < 8; j++) acc[i][j] = 0ull;

        #pragma unroll 2
        for (int d2 = 0; d2 < 64; d2++) {
            unsigned long long a[8], b[8];
            const ulonglong2* za = (const ulonglong2*)(zs + d2 * 128 + ty * 8);
            const ulonglong2* cbase = (const ulonglong2*)(cs + d2 * 128);
            #pragma unroll
            for (int c = 0; c < 4; c++) {
                ulonglong2 av = za[c];
                a[2 * c] = av.x; a[2 * c + 1] = av.y;
                ulonglong2 bv = cbase[tx + 16 * c];
                b[2 * c] = bv.x; b[2 * c + 1] = bv.y;
            }
            #pragma unroll
            for (int i = 0; i < 8; i++)
                #pragma unroll
                for (int j = 0; j < 8; j++)
                    fma_f32x2(acc[i][j], a[i], b[j]);
        }

        float minv[8];
        int   mini[8];
        #pragma unroll
        for (int i = 0; i < 8; i++) { minv[i] = 3.4e38f; mini[i] = 0; }

        #pragma unroll
        for (int j = 0; j < 8; j++) {
            int kg = kt * 128 + 32 * (j >> 1) + 2 * tx + (j & 1);
            float cn = g_cnorm[kg];
            #pragma unroll
            for (int i = 0; i < 8; i++) {
                float s = fmaf(-2.0f, pair_sum(acc[i][j]), cn);
                if (s < minv[i]) { minv[i] = s; mini[i] = kg; }
            }
        }

        __syncthreads();
        float* rv = (float*)cs;               // [16][132]
        int*   ri = (int*)(rv + 16 * 132);
        #pragma unroll
        for (int i = 0; i < 8; i++) {
            int m = ty * 8 + i;
            rv[tx * 132 + m] = minv[i];
            ri[tx * 132 + m] = mini[i];
        }
        __syncthreads();
        if (tid < 128) {
            float bv = rv[tid];
            int   bi = ri[tid];
            #pragma unroll
            for (int t = 1; t < 16; t++) {
                float v = rv[t * 132 + tid];
                int  id = ri[t * 132 + tid];
                if (v < bv || (v == bv && id < bi)) { bv = v; bi = id; }
            }
            unsigned long long packed =
                ((unsigned long long)fkey(bv) << 32) | (uint32_t)bi;
            atomicMin(&g_rbest[lst[tid]], packed);
        }
        __syncthreads();
    }
}

// ---------------------------------------------------------------------------
// Rescue write (persistent): one warp per flagged row.
// ---------------------------------------------------------------------------
__global__ __launch_bounds__(256, 4)
void rescue_write(const float* __restrict__ cb, float* __restrict__ out) {
    const int cnt = g_rcnt;
    const int gw = blockIdx.x * 8 + (threadIdx.x >> 5);
    const int lane = threadIdx.x & 31;
    const float4* cb4 = (const float4*)cb;
    float4* out4 = (float4*)out;
    for (int r = gw; r < cnt; r += RGRID * 8) {
        int row = g_rlist[r];
        uint32_t idx = (uint32_t)(g_rbest[row] & 0xFFFFFFFFull);
        out4[(size_t)row * 32 + lane] = cb4[(size_t)idx * 32 + lane];
    }
}

// ---------------------------------------------------------------------------
extern "C" void kernel_launch(void* const* d_in, const int* in_sizes, int n_in,
                              void* d_out, int out_size) {
    const float* ze = (const float*)d_in[0];   // [65536, 128]
    const float* cb = (const float*)d_in[1];   // [2048, 128]
    float* out = (float*)d_out;
    (void)in_sizes; (void)n_in; (void)out_size;

    cudaFuncSetAttribute(vq_main,
                         cudaFuncAttributeMaxDynamicSharedMemorySize, SMEM_BYTES);
    cudaFuncSetAttribute(rescue_scan,
                         cudaFuncAttributeMaxDynamicSharedMemorySize, RS2_BYTES);

    prep_kernel<<<136, 256>>>(cb);
    vq_main<<<NWIN / MT, 256, SMEM_BYTES>>>(ze, cb, out);
    rescue_scan<<<RGRID, 256, RS2_BYTES>>>(ze, cb);
    rescue_write<<<RGRID, 256>>>(cb, out);
}

// round 10
// speedup vs baseline: 2.7745x; 1.0001x over previous
#include <cuda_runtime.h>
#include <cuda_fp16.h>
#include <cstdint>

// ---------------------------------------------------------------------------
// Problem constants
// ---------------------------------------------------------------------------
#define NWIN   65536
#define DIM    128
#define KCB    2048
#define MT     128              // windows per CTA
#define NSTG   32               // stages: (tile, k64-chunk)
#define STG_UINTS 4096          // one stage = 16 KB fp16 frag image

// main-kernel smem layout (float offsets)
#define ZH_OFF   0              // zh fp16 frag image
#define BB_OFF   8192           // B double buffer: 2 x 4096 uints
#define CN_OFF   16384          // 2048 codebook norms
#define SMEM_FLOATS 18432
#define SMEM_BYTES  (SMEM_FLOATS * 4)

#define TAU 0.18f               // rescue threshold on approx min2-min1 gap

__device__ float    g_cnorm[KCB];
__device__ uint32_t g_Bimg[NSTG * STG_UINTS];   // 512 KB fp16 fragment image
__device__ int      g_rcnt;
__device__ int      g_rlist[NWIN];
__device__ unsigned long long g_rbest[NWIN];    // packed (score-key<<32)|idx

// ---------------------------------------------------------------------------
// Helpers
// ---------------------------------------------------------------------------
__device__ __forceinline__ uint32_t smem_u32(const void* p) {
    uint32_t a;
    asm("{ .reg .u64 t; cvta.to.shared.u64 t, %1; cvt.u32.u64 %0, t; }"
        : "=r"(a) : "l"(p));
    return a;
}
__device__ __forceinline__ void fma_f32x2(unsigned long long& acc,
                                          unsigned long long a,
                                          unsigned long long b) {
    asm("fma.rn.f32x2 %0, %1, %2, %0;" : "+l"(acc) : "l"(a), "l"(b));
}
__device__ __forceinline__ float pair_sum(unsigned long long p) {
    return __uint_as_float((unsigned)(p & 0xFFFFFFFFull))
         + __uint_as_float((unsigned)(p >> 32));
}
// monotone float -> sortable u32 (ascending float == ascending uint)
__device__ __forceinline__ uint32_t fkey(float s) {
    uint32_t b = __float_as_uint(s);
    return b ^ ((uint32_t)((int32_t)b >> 31) | 0x80000000u);
}

// m16n8k16 fp16 MMA, fp32 accum: D += A*B
#define MMA16(d, a, b) \
    asm volatile("mma.sync.aligned.m16n8k16.row.col.f32.f16.f16.f32 " \
        "{%0,%1,%2,%3},{%4,%5,%6,%7},{%8,%9},{%0,%1,%2,%3};" \
        : "+f"((d)[0]), "+f"((d)[1]), "+f"((d)[2]), "+f"((d)[3]) \
        : "r"((a)[0]), "r"((a)[1]), "r"((a)[2]), "r"((a)[3]), \
          "r"((b)[0]), "r"((b)[1]))

#define CP16(dst, src) \
    asm volatile("cp.async.cg.shared.global [%0], [%1], 16;" \
                 :: "r"(dst), "l"(src) : "memory")
#define CP_COMMIT() asm volatile("cp.async.commit_group;" ::: "memory")

// ---------------------------------------------------------------------------
// Merged prep: blocks 0..127 build the fp16 B fragment image (quarter-stage
// each); blocks 128..135 compute codebook norms (1 thread per row).
// ---------------------------------------------------------------------------
__global__ __launch_bounds__(256) void prep_kernel(const float* __restrict__ cb) {
    const int b = blockIdx.x;
    if (b < 128) {
        const int stg = b >> 2;
        const int q   = b & 3;
        const int t = stg >> 1, kc = stg & 1;
        for (int ii = threadIdx.x; ii < 1024; ii += 256) {
            int i = q * 1024 + ii;
            int reg  = i & 1;
            int lane = (i >> 1) & 31;
            int f    = (i >> 6) & 15;
            int ks   = (i >> 10) & 3;
            int n  = t * 128 + f * 8 + (lane >> 2);
            int k0 = kc * 64 + ks * 16 + reg * 8 + (lane & 3) * 2;
            __half h0 = __float2half_rn(cb[(size_t)n * DIM + k0]);
            __half h1 = __float2half_rn(cb[(size_t)n * DIM + k0 + 1]);
            g_Bimg[(size_t)stg * STG_UINTS + i] =
                (uint32_t)__half_as_ushort(h0)
                | ((uint32_t)__half_as_ushort(h1) << 16);
        }
    } else {
        if (b == 128 && threadIdx.x == 0) g_rcnt = 0;
        int row = (b - 128) * 256 + threadIdx.x;   // 8 blocks x 256 = 2048 rows
        const float4* r4 = (const float4*)(cb + (size_t)row * DIM);
        float s = 0.0f;
        #pragma unroll 8
        for (int j = 0; j < 32; j++) {
            float4 v = r4[j];
            s += v.x * v.x + v.y * v.y + v.z * v.z + v.w * v.w;
        }
        g_cnorm[row] = s;
    }
}

// ---------------------------------------------------------------------------
// Main kernel: fp16 approx GEMM + top-2 argmin + flagging. (unchanged fast path)
// ---------------------------------------------------------------------------
__global__ __launch_bounds__(256, 2)
void vq_main(const float* __restrict__ ze,
             const float* __restrict__ cb,
             float* __restrict__ out) {
    extern __shared__ float sm[];
    const uint32_t sb = smem_u32(sm);
    const int tid  = threadIdx.x;
    const int wid  = tid >> 5;
    const int lane = tid & 31;
    const int wm   = wid & 1;
    const int wn   = wid >> 1;
    const int m0   = blockIdx.x * MT;

    {
        const uint32_t* src = g_Bimg + tid * 4;
        uint32_t dst = sb + (BB_OFF + tid * 4) * 4;
        #pragma unroll
        for (int j = 0; j < 4; j++) CP16(dst + j * 4096, src + j * 1024);
        CP_COMMIT();
    }

    for (int i = tid; i < KCB; i += 256) sm[CN_OFF + i] = g_cnorm[i];

    {
        __half* ZHh = (__half*)(sm + ZH_OFF);
        for (int i = tid; i < MT * DIM; i += 256) {
            int m = i >> 7, k = i & 127;
            float v = ze[(size_t)(m0 + m) * DIM + k];
            int ks = k >> 4, kk = k & 15, mf = m >> 4, r = m & 15;
            int lan = ((r & 7) << 2) | ((kk >> 1) & 3);
            int reg = ((kk >> 3) << 1) | (r >> 3);
            int h   = kk & 1;
            ZHh[(((ks * 8 + mf) * 32 + lan) * 4 + reg) * 2 + h] = __float2half_rn(v);
        }
    }

    float acc[4][4][4];
    #pragma unroll
    for (int a = 0; a < 4; a++)
        #pragma unroll
        for (int b = 0; b < 4; b++)
            #pragma unroll
            for (int c = 0; c < 4; c++) acc[a][b][c] = 0.0f;

    float minv[8], minv2[8];
    int   mini[8];
    #pragma unroll
    for (int i = 0; i < 8; i++) { minv[i] = 3.4e38f; minv2[i] = 3.4e38f; mini[i] = 0; }

    const uint4* ZH = (const uint4*)(sm + ZH_OFF);

    for (int st = 0; st < NSTG; st++) {
        if (st < NSTG - 1) {
            const uint32_t* src = g_Bimg + (size_t)(st + 1) * STG_UINTS + tid * 4;
            uint32_t dst = sb + (BB_OFF + ((st + 1) & 1) * STG_UINTS + tid * 4) * 4;
            #pragma unroll
            for (int j = 0; j < 4; j++) CP16(dst + j * 4096, src + j * 1024);
            CP_COMMIT();
            asm volatile("cp.async.wait_group 1;" ::: "memory");
        } else {
            asm volatile("cp.async.wait_group 0;" ::: "memory");
        }
        __syncthreads();

        const uint2* Bp = (const uint2*)(sm + BB_OFF + (st & 1) * STG_UINTS);
        const int kc = st & 1;

        #pragma unroll
        for (int s = 0; s < 4; s++) {
            const int ksg = kc * 4 + s;
            uint32_t ah[4][4], bh[4][2];
            #pragma unroll
            for (int mf = 0; mf < 4; mf++) {
                uint4 h = ZH[(ksg * 8 + wm * 4 + mf) * 32 + lane];
                ah[mf][0] = h.x; ah[mf][1] = h.y; ah[mf][2] = h.z; ah[mf][3] = h.w;
            }
            #pragma unroll
            for (int f = 0; f < 4; f++) {
                uint2 h = Bp[(s * 16 + wn * 4 + f) * 32 + lane];
                bh[f][0] = h.x; bh[f][1] = h.y;
            }
            #pragma unroll
            for (int mf = 0; mf < 4; mf++)
                #pragma unroll
                for (int f = 0; f < 4; f++)
                    MMA16(acc[mf][f], ah[mf], bh[f]);
        }

        if (st & 1) {
            const int kb = (st >> 1) * 128 + wn * 32 + 2 * (lane & 3);
            #pragma unroll
            for (int mf = 0; mf < 4; mf++)
                #pragma unroll
                for (int f = 0; f < 4; f++)
                    #pragma unroll
                    for (int c = 0; c < 4; c++) {
                        int kn = kb + f * 8 + (c & 1);
                        float sc = fmaf(-2.0f, acc[mf][f][c], sm[CN_OFF + kn]);
                        int i = mf * 2 + (c >> 1);
                        if (sc < minv[i]) {
                            minv2[i] = minv[i]; minv[i] = sc; mini[i] = kn;
                        } else if (sc < minv2[i]) {
                            minv2[i] = sc;
                        }
                        acc[mf][f][c] = 0.0f;
                    }
        }
        __syncthreads();
    }

    float* rv1  = sm + BB_OFF;
    int*   ri1  = (int*)(sm + BB_OFF + 2048);
    float* rv2  = sm + BB_OFF + 4096;
    int*   fidx = (int*)(sm + BB_OFF + 6144);
    #pragma unroll
    for (int i = 0; i < 8; i++) {
        int mfl = i >> 1, rh = i & 1;
        int m = wm * 64 + mfl * 16 + rh * 8 + (lane >> 2);
        int slot = wn * 4 + (lane & 3);
        rv1[m * 16 + slot] = minv[i];
        ri1[m * 16 + slot] = mini[i];
        rv2[m * 16 + slot] = minv2[i];
    }
    __syncthreads();
    if (tid < MT) {
        float m1 = rv1[tid * 16], m2 = rv2[tid * 16];
        int   i1 = ri1[tid * 16];
        #pragma unroll
        for (int t = 1; t < 16; t++) {
            float v1 = rv1[tid * 16 + t], v2 = rv2[tid * 16 + t];
            int  id = ri1[tid * 16 + t];
            if (v1 < m1 || (v1 == m1 && id < i1)) {
                m2 = fminf(m1, v2); m1 = v1; i1 = id;
            } else {
                m2 = fminf(m2, v1);
            }
        }
        fidx[tid] = i1;
        if (m2 - m1 < TAU) {
            g_rbest[m0 + tid] = ~0ull;         // init merge slot
            int p = atomicAdd(&g_rcnt, 1);
            g_rlist[p] = m0 + tid;
        }
    }
    __syncthreads();

    const float4* cb4 = (const float4*)cb;
    float4* out4 = (float4*)out;
    for (int i = tid; i < MT * (DIM / 4); i += 256) {
        int m = i >> 5, c = i & 31;
        out4[(size_t)(m0 + m) * 32 + c] = cb4[(size_t)fidx[m] * 32 + c];
    }
}

// ---------------------------------------------------------------------------
// Rescue scan (persistent): exact fp32, k-split. Work item = (row-block bx,
// k-tile kt). 148 blocks loop over items; per item: 128 gathered rows x 128
// codes, 8x8 f32x2 register tiling, atomicMin merge of (score-key, idx).
// ---------------------------------------------------------------------------
#define RS2_LST  (2 * 64 * 128)               // ull offset of row list
#define RS2_BYTES (2 * 64 * 128 * 8 + 512 + 64)
#define RGRID 148

__global__ __launch_bounds__(256, 1)
void rescue_scan(const float* __restrict__ ze,
                 const float* __restrict__ cb) {
    const int cnt = g_rcnt;
    const int nbx = (cnt + 127) >> 7;
    const int total = nbx * 16;

    extern __shared__ unsigned long long rsm[];
    unsigned long long* zs = rsm;             // [64][128] (d2, row)
    unsigned long long* cs = rsm + 64 * 128;  // [64][128] (d2, code)
    int* lst = (int*)(rsm + RS2_LST);

    const int tid = threadIdx.x;
    const int tx  = tid & 15;
    const int ty  = tid >> 4;

    for (int item = blockIdx.x; item < total; item += RGRID) {
        const int bx = item >> 4;
        const int kt = item & 15;
        const int base = bx * 128;

        if (tid < 128) {
            int p = base + tid;
            lst[tid] = g_rlist[p < cnt ? p : base];
        }
        __syncthreads();

        for (int i = tid; i < 128 * 64; i += 256) {
            int m = i >> 6, d2 = i & 63;
            zs[d2 * 128 + m] =
                ((const unsigned long long*)(ze + (size_t)lst[m] * DIM))[d2];
        }
        {
            const unsigned long long* cg =
                (const unsigned long long*)(cb + (size_t)kt * 128 * DIM);
            for (int i = tid; i < 128 * 64; i += 256) {
                int k = i >> 6, d2 = i & 63;
                cs[d2 * 128 + k] = cg[i];
            }
        }
        __syncthreads();

        unsigned long long acc[8][8];
        #pragma unroll
        for (int i = 0; i < 8; i++)
            #pragma unroll
            for (int j = 0; j < 8; j++) acc[i][j] = 0ull;

        #pragma unroll 2
        for (int d2 = 0; d2 < 64; d2++) {
            unsigned long long a[8], b[8];
            const ulonglong2* za = (const ulonglong2*)(zs + d2 * 128 + ty * 8);
            const ulonglong2* cbase = (const ulonglong2*)(cs + d2 * 128);
            #pragma unroll
            for (int c = 0; c < 4; c++) {
                ulonglong2 av = za[c];
                a[2 * c] = av.x; a[2 * c + 1] = av.y;
                ulonglong2 bv = cbase[tx + 16 * c];
                b[2 * c] = bv.x; b[2 * c + 1] = bv.y;
            }
            #pragma unroll
            for (int i = 0; i < 8; i++)
                #pragma unroll
                for (int j = 0; j < 8; j++)
                    fma_f32x2(acc[i][j], a[i], b[j]);
        }

        float minv[8];
        int   mini[8];
        #pragma unroll
        for (int i = 0; i < 8; i++) { minv[i] = 3.4e38f; mini[i] = 0; }

        #pragma unroll
        for (int j = 0; j < 8; j++) {
            int kg = kt * 128 + 32 * (j >> 1) + 2 * tx + (j & 1);
            float cn = g_cnorm[kg];
            #pragma unroll
            for (int i = 0; i < 8; i++) {
                float s = fmaf(-2.0f, pair_sum(acc[i][j]), cn);
                if (s < minv[i]) { minv[i] = s; mini[i] = kg; }
            }
        }

        __syncthreads();
        float* rv = (float*)cs;               // [16][132]
        int*   ri = (int*)(rv + 16 * 132);
        #pragma unroll
        for (int i = 0; i < 8; i++) {
            int m = ty * 8 + i;
            rv[tx * 132 + m] = minv[i];
            ri[tx * 132 + m] = mini[i];
        }
        __syncthreads();
        if (tid < 128) {
            float bv = rv[tid];
            int   bi = ri[tid];
            #pragma unroll
            for (int t = 1; t < 16; t++) {
                float v = rv[t * 132 + tid];
                int  id = ri[t * 132 + tid];
                if (v < bv || (v == bv && id < bi)) { bv = v; bi = id; }
            }
            unsigned long long packed =
                ((unsigned long long)fkey(bv) << 32) | (uint32_t)bi;
            atomicMin(&g_rbest[lst[tid]], packed);
        }
        __syncthreads();
    }
}

// ---------------------------------------------------------------------------
// Rescue write (persistent): one warp per flagged row.
// ---------------------------------------------------------------------------
__global__ __launch_bounds__(256, 4)
void rescue_write(const float* __restrict__ cb, float* __restrict__ out) {
    const int cnt = g_rcnt;
    const int gw = blockIdx.x * 8 + (threadIdx.x >> 5);
    const int lane = threadIdx.x & 31;
    const float4* cb4 = (const float4*)cb;
    float4* out4 = (float4*)out;
    for (int r = gw; r < cnt; r += RGRID * 8) {
        int row = g_rlist[r];
        uint32_t idx = (uint32_t)(g_rbest[row] & 0xFFFFFFFFull);
        out4[(size_t)row * 32 + lane] = cb4[(size_t)idx * 32 + lane];
    }
}

// ---------------------------------------------------------------------------
extern "C" void kernel_launch(void* const* d_in, const int* in_sizes, int n_in,
                              void* d_out, int out_size) {
    const float* ze = (const float*)d_in[0];   // [65536, 128]
    const float* cb = (const float*)d_in[1];   // [2048, 128]
    float* out = (float*)d_out;
    (void)in_sizes; (void)n_in; (void)out_size;

    cudaFuncSetAttribute(vq_main,
                         cudaFuncAttributeMaxDynamicSharedMemorySize, SMEM_BYTES);
    cudaFuncSetAttribute(rescue_scan,
                         cudaFuncAttributeMaxDynamicSharedMemorySize, RS2_BYTES);

    prep_kernel<<<136, 256>>>(cb);
    vq_main<<<NWIN / MT, 256, SMEM_BYTES>>>(ze, cb, out);
    rescue_scan<<<RGRID, 256, RS2_BYTES>>>(ze, cb);
    rescue_write<<<RGRID, 256>>>(cb, out);
}